// round 10
// baseline (speedup 1.0000x reference)
#include <cuda_runtime.h>

// Problem constants
#define NB      4
#define NDET    128
#define NT      2048
#define NPIX    65536            // 256*256
#define DC      4                // dets per chunk (SMEM = DC*NT*16B = 128KB)
#define NCHUNK  32               // NDET / DC
#define PT      8                // pixel tiles
#define PPT     8192             // NPIX / PT
#define THREADS 1024
#define NPASS   16               // passes per warp: 256 px/warp, 16 px/pass

// Scratch (static __device__ — no allocations allowed)
__device__ float4 g_scratch[NPIX];   // [pixel] -> 4 batch sums   1 MB

// ---------------------------------------------------------------------------
// Packed f32x2 helpers (Blackwell dual-FMA).
// ---------------------------------------------------------------------------
__device__ __forceinline__ unsigned long long pk2(float lo, float hi) {
    unsigned long long r;
    asm("mov.b64 %0, {%1, %2};" : "=l"(r) : "f"(lo), "f"(hi));
    return r;
}
__device__ __forceinline__ void upk2(unsigned long long v, float& lo, float& hi) {
    asm("mov.b64 {%0, %1}, %2;" : "=f"(lo), "=f"(hi) : "l"(v));
}
__device__ __forceinline__ unsigned long long fma2(unsigned long long a,
                                                   unsigned long long b,
                                                   unsigned long long c) {
    unsigned long long d;
    asm("fma.rn.f32x2 %0, %1, %2, %3;" : "=l"(d) : "l"(a), "l"(b), "l"(c));
    return d;
}

// ---------------------------------------------------------------------------
// Zero scratch (1 MB) before atomic accumulation.
// ---------------------------------------------------------------------------
__global__ void __launch_bounds__(1024)
zero_scratch_kernel() {
    int i = blockIdx.x * blockDim.x + threadIdx.x;
    if (i < NPIX) g_scratch[i] = make_float4(0.f, 0.f, 0.f, 0.f);
}

// ---------------------------------------------------------------------------
// Main backprojection kernel.
// grid = (PT, NCHUNK) = 256 blocks x 1024 threads, 128 KB dynamic SMEM.
// Stage 4 det rows (batch-transposed float4 from L2-resident sino), sync.
// Then warp-cooperative pixel passes: 16 pixels x 2 lanes per pass. One
// LDG.128 per pass fetches the full 32B lut for 16 pixels (16 line-touches
// instead of 32 -> half the L1tex wavefronts). Each lane handles 2 dets
// (4 LDS.128), pair is reduced with shfl_xor, even lane issues one
// red.global.add.v4.f32 into [pixel]-major scratch.
// ---------------------------------------------------------------------------
extern __shared__ float4 s_sino[];   // [DC][NT]  128 KB

__global__ void __launch_bounds__(THREADS, 1)
bp_main_kernel(const float* __restrict__ sino,
               const float4* __restrict__ lut4) {
    const int tid   = threadIdx.x;
    const int warp  = tid >> 5;
    const int lane  = tid & 31;
    const int q     = lane >> 1;        // pixel within pass (0..15)
    const int r     = lane & 1;         // det-half (0: dets 0-1, 1: dets 2-3)
    const int pbase = blockIdx.x * PPT;
    const int c     = blockIdx.y;       // det chunk

    // Stage DC det rows, transposing batches into float4 on the fly.
    #pragma unroll 8
    for (int i = tid; i < DC * NT; i += THREADS) {
        int j = i >> 11;            // det within chunk
        int k = i & (NT - 1);
        const float* sp = sino + (size_t)(c * DC + j) * NT + k;
        float4 v;
        v.x = __ldg(sp + 0 * NDET * NT);
        v.y = __ldg(sp + 1 * NDET * NT);
        v.z = __ldg(sp + 2 * NDET * NT);
        v.w = __ldg(sp + 3 * NDET * NT);
        s_sino[i] = v;
    }

    // Hann weights for this lane's 2 dets, pre-divided by norm (=63.5).
    const int j0 = 2 * r;               // smem det row of first det
    float ap0, ap1;
    {
        int d0 = c * DC + j0;
        ap0 = (0.5f - 0.5f * cosf(6.2831853071795864769f * (float)d0 / 127.0f))
              * (1.0f / 63.5f);
        ap1 = (0.5f - 0.5f * cosf(6.2831853071795864769f * (float)(d0 + 1) / 127.0f))
              * (1.0f / 63.5f);
    }

    __syncthreads();

    // Warp's first pixel; passes advance by 16 pixels.
    const int wbase = pbase + warp * (NPASS * 16);
    // lut float4 index for (pixel, this lane): pixel*64 + c*2 + r
    const float4* __restrict__ lp = lut4 + (size_t)(wbase + q) * 64
                                         + (size_t)c * 2 + r;

    float4 la = __ldg(lp);              // pass 0 prefetch

    #pragma unroll
    for (int pass = 0; pass < NPASS; pass++) {
        float4 na = la;
        if (pass + 1 < NPASS) na = __ldg(lp + (size_t)(pass + 1) * (16 * 64));

        // This lane's 2 dets: (k,alpha) pairs.
        float kf0 = la.x, al0 = la.y;
        float kf1 = la.z, al1 = la.w;

        unsigned long long acc_xy = 0ull, acc_zw = 0ull;

        {   // det j0
            int k = (int)kf0;
            bool valid = ((unsigned)k < (unsigned)(NT - 1));
            int k0 = min(max(k, 0), NT - 2);
            float4 s0 = s_sino[j0 * NT + k0];
            float4 s1 = s_sino[j0 * NT + k0 + 1];
            float w  = valid ? ap0 : 0.0f;
            float wa = w * al0;
            float w0 = w - wa;
            unsigned long long w0p = pk2(w0, w0), wap = pk2(wa, wa);
            acc_xy = fma2(w0p, pk2(s0.x, s0.y), fma2(wap, pk2(s1.x, s1.y), acc_xy));
            acc_zw = fma2(w0p, pk2(s0.z, s0.w), fma2(wap, pk2(s1.z, s1.w), acc_zw));
        }
        {   // det j0+1
            int k = (int)kf1;
            bool valid = ((unsigned)k < (unsigned)(NT - 1));
            int k0 = min(max(k, 0), NT - 2);
            float4 s0 = s_sino[(j0 + 1) * NT + k0];
            float4 s1 = s_sino[(j0 + 1) * NT + k0 + 1];
            float w  = valid ? ap1 : 0.0f;
            float wa = w * al1;
            float w0 = w - wa;
            unsigned long long w0p = pk2(w0, w0), wap = pk2(wa, wa);
            acc_xy = fma2(w0p, pk2(s0.x, s0.y), fma2(wap, pk2(s1.x, s1.y), acc_xy));
            acc_zw = fma2(w0p, pk2(s0.z, s0.w), fma2(wap, pk2(s1.z, s1.w), acc_zw));
        }

        float ax, ay, az, aw;
        upk2(acc_xy, ax, ay);
        upk2(acc_zw, az, aw);

        // Combine the lane pair (r=0 gets r=1's partial and vice versa).
        ax += __shfl_xor_sync(0xFFFFFFFFu, ax, 1);
        ay += __shfl_xor_sync(0xFFFFFFFFu, ay, 1);
        az += __shfl_xor_sync(0xFFFFFFFFu, az, 1);
        aw += __shfl_xor_sync(0xFFFFFFFFu, aw, 1);

        // Even lane sinks one vector atomic (16 lanes x 16B, 256B contiguous).
        if (r == 0) {
            float* ptr = (float*)(g_scratch + (wbase + pass * 16 + q));
            asm volatile("red.global.add.v4.f32 [%0], {%1, %2, %3, %4};"
                         :: "l"(ptr), "f"(ax), "f"(ay), "f"(az), "f"(aw)
                         : "memory");
        }

        la = na;
    }
}

// ---------------------------------------------------------------------------
// Transpose scratch [pixel][batch] -> out [batch][pixel].
// ---------------------------------------------------------------------------
__global__ void __launch_bounds__(1024)
bp_finish_kernel(float* __restrict__ out) {
    int p = blockIdx.x * blockDim.x + threadIdx.x;
    if (p >= NPIX) return;
    float4 v = g_scratch[p];
    out[0 * NPIX + p] = v.x;
    out[1 * NPIX + p] = v.y;
    out[2 * NPIX + p] = v.z;
    out[3 * NPIX + p] = v.w;
}

// ---------------------------------------------------------------------------
extern "C" void kernel_launch(void* const* d_in, const int* in_sizes, int n_in,
                              void* d_out, int out_size) {
    const float*  sino = (const float*)d_in[0];
    const float4* lut4 = (const float4*)d_in[1];
    float*        out  = (float*)d_out;

    cudaFuncSetAttribute(bp_main_kernel,
                         cudaFuncAttributeMaxDynamicSharedMemorySize,
                         DC * NT * (int)sizeof(float4));

    zero_scratch_kernel<<<NPIX / 1024, 1024>>>();

    dim3 grid(PT, NCHUNK);
    bp_main_kernel<<<grid, THREADS, DC * NT * sizeof(float4)>>>(sino, lut4);

    bp_finish_kernel<<<NPIX / 1024, 1024>>>(out);
}

// round 12
// speedup vs baseline: 1.6409x; 1.6409x over previous
#include <cuda_runtime.h>

// Problem constants
#define NB      4
#define NDET    128
#define NT      2048
#define NPIX    65536            // 256*256
#define DC      4                // dets per chunk (SMEM = DC*NT*16B = 128KB)
#define NCHUNK  32               // NDET / DC
#define PT      8                // pixel tiles
#define PPT     8192             // NPIX / PT
#define THREADS 1024
#define PPTH    8                // pixels per thread = PPT / THREADS

// Scratch (static __device__ — no allocations allowed)
__device__ uint4 g_lutP[NCHUNK * NPIX];   // 16 MB packed lut [chunk][pixel]

// ---------------------------------------------------------------------------
// Packed f32x2 helpers (Blackwell dual-FMA).
// ---------------------------------------------------------------------------
__device__ __forceinline__ unsigned long long pk2(float lo, float hi) {
    unsigned long long r;
    asm("mov.b64 %0, {%1, %2};" : "=l"(r) : "f"(lo), "f"(hi));
    return r;
}
__device__ __forceinline__ void upk2(unsigned long long v, float& lo, float& hi) {
    asm("mov.b64 {%0, %1}, %2;" : "=f"(lo), "=f"(hi) : "l"(v));
}
__device__ __forceinline__ unsigned long long fma2(unsigned long long a,
                                                   unsigned long long b,
                                                   unsigned long long c) {
    unsigned long long d;
    asm("fma.rn.f32x2 %0, %1, %2, %3;" : "=l"(d) : "l"(a), "l"(b), "l"(c));
    return d;
}

// Pack (k_floor, alpha): bits[0:11)=k0 clamped, bit11=valid, bits[12:32)=alpha q20.
__device__ __forceinline__ unsigned pack_lut(float kf, float a) {
    int k = (int)kf;
    unsigned valid = ((unsigned)k < 2047u) ? (1u << 11) : 0u;   // 0 <= k < NT-1
    int k0 = min(max(k, 0), NT - 2);
    unsigned aq = (unsigned)(a * 1048576.0f);
    if (aq > 1048575u) aq = 1048575u;
    return (unsigned)k0 | valid | (aq << 12);
}

// ---------------------------------------------------------------------------
// Kernel 1: pack + transpose lut [pixel][64 f4] -> [chunk][pixel] uint4.
// 1024 blocks x 512 threads; each thread: 8 coalesced float4 loads (MLP=8),
// pack to uint2, padded SMEM transpose, coalesced uint4 stores (16
// consecutive uint4 per half-warp store phase). Also zeroes d_out (atomics
// target), replacing a separate launch.
// ---------------------------------------------------------------------------
__global__ void __launch_bounds__(512)
lut_pack_kernel(const float4* __restrict__ lut4, float4* __restrict__ outz) {
    __shared__ uint2 tile[64][65];          // [px_local][f]  ~33 KB, padded
    const int t = threadIdx.x;
    const size_t base = (size_t)blockIdx.x * 4096;   // 64 pixels x 64 f

    // Zero this block's slice of d_out (65536 float4 total / 1024 blocks).
    if (t < 64) outz[blockIdx.x * 64 + t] = make_float4(0.f, 0.f, 0.f, 0.f);

    #pragma unroll
    for (int i = 0; i < 8; i++) {
        int n = t + i * 512;
        float4 v = __ldg(lut4 + base + n);
        uint2 u;
        u.x = pack_lut(v.x, v.y);
        u.y = pack_lut(v.z, v.w);
        tile[n >> 6][n & 63] = u;
    }
    __syncthreads();

    const int c   = t >> 4;                 // chunk 0..31
    const int pl0 = t & 15;
    const size_t pbase = (size_t)blockIdx.x * 64;
    #pragma unroll
    for (int j = 0; j < 4; j++) {
        int pl = pl0 + j * 16;
        uint2 a = tile[pl][2 * c];
        uint2 b = tile[pl][2 * c + 1];
        g_lutP[(size_t)c * NPIX + pbase + pl] = make_uint4(a.x, a.y, b.x, b.y);
    }
}

// ---------------------------------------------------------------------------
// Kernel 2: main backprojection (round-9 structure, packed-lut source).
// grid = (PT, NCHUNK) = 256 blocks x 1024 threads, 128 KB dynamic SMEM.
// Stage 4 det rows (batch-transposed float4 from L2-resident sino), sync,
// 8 pixels/thread. lut read is now ONE coalesced LDG.128 per pixel-chunk
// (4 lines/warp-instr vs 64). FFMA2 math, scalar no-return atomics to out.
// ---------------------------------------------------------------------------
extern __shared__ float4 s_sino[];   // [DC][NT]  128 KB

__global__ void __launch_bounds__(THREADS, 1)
bp_main_kernel(const float* __restrict__ sino, float* __restrict__ out) {
    const int tid   = threadIdx.x;
    const int pbase = blockIdx.x * PPT;
    const int c     = blockIdx.y;          // det chunk

    // Stage DC det rows, transposing batches into float4 on the fly.
    #pragma unroll 8
    for (int i = tid; i < DC * NT; i += THREADS) {
        int j = i >> 11;            // det within chunk
        int k = i & (NT - 1);
        const float* sp = sino + (size_t)(c * DC + j) * NT + k;
        float4 v;
        v.x = __ldg(sp + 0 * NDET * NT);
        v.y = __ldg(sp + 1 * NDET * NT);
        v.z = __ldg(sp + 2 * NDET * NT);
        v.w = __ldg(sp + 3 * NDET * NT);
        s_sino[i] = v;
    }

    // Hann weights, pre-divided by the exact norm (sum apod = 63.5).
    float apod[DC];
    #pragma unroll
    for (int j = 0; j < DC; j++) {
        int d = c * DC + j;
        apod[j] = (0.5f - 0.5f * cosf(6.2831853071795864769f * (float)d / 127.0f))
                  * (1.0f / 63.5f);
    }

    __syncthreads();

    const uint4* __restrict__ lp = g_lutP + (size_t)c * NPIX + pbase;

    // Prefetch pixel 0's packed lut.
    uint4 L = __ldg(lp + tid);

    #pragma unroll
    for (int pp = 0; pp < PPTH; pp++) {
        uint4 N = L;
        if (pp + 1 < PPTH) N = __ldg(lp + (pp + 1) * THREADS + tid);

        unsigned u[DC] = {L.x, L.y, L.z, L.w};

        unsigned long long acc_xy = 0ull, acc_zw = 0ull;

        #pragma unroll
        for (int j = 0; j < DC; j++) {
            unsigned v = u[j];
            int   k0 = (int)(v & 0x7FFu);                  // 0..2046
            float w  = (v & 0x800u) ? apod[j] : 0.0f;
            float a  = (float)(v >> 12) * (1.0f / 1048576.0f);

            float4 s0 = s_sino[j * NT + k0];
            float4 s1 = s_sino[j * NT + k0 + 1];

            float wa = w * a;
            float w0 = w - wa;

            unsigned long long w0p = pk2(w0, w0), wap = pk2(wa, wa);
            acc_xy = fma2(w0p, pk2(s0.x, s0.y), fma2(wap, pk2(s1.x, s1.y), acc_xy));
            acc_zw = fma2(w0p, pk2(s0.z, s0.w), fma2(wap, pk2(s1.z, s1.w), acc_zw));
        }

        float ax, ay, az, aw;
        upk2(acc_xy, ax, ay);
        upk2(acc_zw, az, aw);

        // Coalesced no-return float atomics into out[batch][pixel].
        const int p = pbase + pp * THREADS + tid;
        atomicAdd(out + 0 * NPIX + p, ax);
        atomicAdd(out + 1 * NPIX + p, ay);
        atomicAdd(out + 2 * NPIX + p, az);
        atomicAdd(out + 3 * NPIX + p, aw);

        L = N;
    }
}

// ---------------------------------------------------------------------------
extern "C" void kernel_launch(void* const* d_in, const int* in_sizes, int n_in,
                              void* d_out, int out_size) {
    const float*  sino = (const float*)d_in[0];
    const float4* lut4 = (const float4*)d_in[1];
    float*        out  = (float*)d_out;

    cudaFuncSetAttribute(bp_main_kernel,
                         cudaFuncAttributeMaxDynamicSharedMemorySize,
                         DC * NT * (int)sizeof(float4));

    lut_pack_kernel<<<1024, 512>>>(lut4, (float4*)out);

    dim3 grid(PT, NCHUNK);
    bp_main_kernel<<<grid, THREADS, DC * NT * sizeof(float4)>>>(sino, out);
}

// round 13
// speedup vs baseline: 1.8558x; 1.1310x over previous
#include <cuda_runtime.h>

// Problem constants
#define NB      4
#define NDET    128
#define NT      2048
#define NPIX    65536            // 256*256
#define DC      4                // dets per chunk (SMEM = DC*NT*16B = 128KB)
#define NCHUNK  32               // NDET / DC
#define THREADS 1024
#define TOTALW  (NCHUNK * NPIX)  // 2,097,152 px-chunk work units
#define WPB     14336            // work per block (14 * 1024), 1024-aligned
#define NBLK    ((TOTALW + WPB - 1) / WPB)   // 147 blocks -> 1 wave on 148 SMs

// Scratch (static __device__ — no allocations allowed)
__device__ uint4 g_lutP[NCHUNK * NPIX];   // 16 MB packed lut [chunk][pixel]

// ---------------------------------------------------------------------------
// Packed f32x2 helpers (Blackwell dual-FMA).
// ---------------------------------------------------------------------------
__device__ __forceinline__ unsigned long long pk2(float lo, float hi) {
    unsigned long long r;
    asm("mov.b64 %0, {%1, %2};" : "=l"(r) : "f"(lo), "f"(hi));
    return r;
}
__device__ __forceinline__ void upk2(unsigned long long v, float& lo, float& hi) {
    asm("mov.b64 {%0, %1}, %2;" : "=f"(lo), "=f"(hi) : "l"(v));
}
__device__ __forceinline__ unsigned long long fma2(unsigned long long a,
                                                   unsigned long long b,
                                                   unsigned long long c) {
    unsigned long long d;
    asm("fma.rn.f32x2 %0, %1, %2, %3;" : "=l"(d) : "l"(a), "l"(b), "l"(c));
    return d;
}

// Pack (k_floor, alpha): bits[0:11)=k0 clamped, bit11=valid, bits[12:32)=alpha q20.
__device__ __forceinline__ unsigned pack_lut(float kf, float a) {
    int k = (int)kf;
    unsigned valid = ((unsigned)k < 2047u) ? (1u << 11) : 0u;   // 0 <= k < NT-1
    int k0 = min(max(k, 0), NT - 2);
    unsigned aq = (unsigned)(a * 1048576.0f);
    if (aq > 1048575u) aq = 1048575u;
    return (unsigned)k0 | valid | (aq << 12);
}

// ---------------------------------------------------------------------------
// Kernel 1: pack + transpose lut [pixel][64 f4] -> [chunk][pixel] uint4.
// Unchanged from round 12 (measured ~15.5us, near 80MB DRAM floor).
// Also zeroes d_out (atomics target).
// ---------------------------------------------------------------------------
__global__ void __launch_bounds__(512)
lut_pack_kernel(const float4* __restrict__ lut4, float4* __restrict__ outz) {
    __shared__ uint2 tile[64][65];          // [px_local][f]  ~33 KB, padded
    const int t = threadIdx.x;
    const size_t base = (size_t)blockIdx.x * 4096;   // 64 pixels x 64 f

    if (t < 64) outz[blockIdx.x * 64 + t] = make_float4(0.f, 0.f, 0.f, 0.f);

    #pragma unroll
    for (int i = 0; i < 8; i++) {
        int n = t + i * 512;
        float4 v = __ldg(lut4 + base + n);
        uint2 u;
        u.x = pack_lut(v.x, v.y);
        u.y = pack_lut(v.z, v.w);
        tile[n >> 6][n & 63] = u;
    }
    __syncthreads();

    const int c   = t >> 4;                 // chunk 0..31
    const int pl0 = t & 15;
    const size_t pbase = (size_t)blockIdx.x * 64;
    #pragma unroll
    for (int j = 0; j < 4; j++) {
        int pl = pl0 + j * 16;
        uint2 a = tile[pl][2 * c];
        uint2 b = tile[pl][2 * c + 1];
        g_lutP[(size_t)c * NPIX + pbase + pl] = make_uint4(a.x, a.y, b.x, b.y);
    }
}

// ---------------------------------------------------------------------------
// Kernel 2: main backprojection — persistent balanced grid.
// 147 blocks x 1024 threads, one block per SM, single wave. Block b owns
// work units [b*WPB, (b+1)*WPB) in chunk-major (c*NPIX + px) order; it
// stages chunk c (batch-transposed float4 from L2-resident sino), processes
// its 1024-px groups with packed-lut prefetch + FFMA2, re-staging at most
// once when the range crosses a chunk boundary. Coalesced no-return float
// atomics into out[batch][pixel].
// ---------------------------------------------------------------------------
extern __shared__ float4 s_sino[];   // [DC][NT]  128 KB

__global__ void __launch_bounds__(THREADS, 1)
bp_main_kernel(const float* __restrict__ sino, float* __restrict__ out) {
    const int tid = threadIdx.x;

    int w    = blockIdx.x * WPB;
    int wend = min(w + WPB, TOTALW);

    while (w < wend) {
        const int c   = w >> 16;            // w / NPIX
        const int px0 = w & (NPIX - 1);     // w % NPIX
        const int seg_end = min((c + 1) << 16, wend);
        const int ngroups = (seg_end - w) >> 10;   // px count / 1024

        __syncthreads();   // protect SMEM from previous segment's readers

        // Stage DC det rows of chunk c, transposing batches into float4.
        #pragma unroll 8
        for (int i = tid; i < DC * NT; i += THREADS) {
            int j = i >> 11;            // det within chunk
            int k = i & (NT - 1);
            const float* sp = sino + (size_t)(c * DC + j) * NT + k;
            float4 v;
            v.x = __ldg(sp + 0 * NDET * NT);
            v.y = __ldg(sp + 1 * NDET * NT);
            v.z = __ldg(sp + 2 * NDET * NT);
            v.w = __ldg(sp + 3 * NDET * NT);
            s_sino[i] = v;
        }

        // Hann weights, pre-divided by the exact norm (sum apod = 63.5).
        float apod[DC];
        #pragma unroll
        for (int j = 0; j < DC; j++) {
            int d = c * DC + j;
            apod[j] = (0.5f - 0.5f * cosf(6.2831853071795864769f * (float)d / 127.0f))
                      * (1.0f / 63.5f);
        }

        __syncthreads();

        const uint4* __restrict__ lp = g_lutP + (size_t)c * NPIX + px0 + tid;

        // Software-pipelined group loop (lut is L2-resident after pack).
        uint4 L = __ldg(lp);
        for (int g = 0; g < ngroups; g++) {
            uint4 N = L;
            if (g + 1 < ngroups) N = __ldg(lp + (g + 1) * THREADS);

            unsigned u[DC] = {L.x, L.y, L.z, L.w};

            unsigned long long acc_xy = 0ull, acc_zw = 0ull;

            #pragma unroll
            for (int j = 0; j < DC; j++) {
                unsigned v = u[j];
                int   k0 = (int)(v & 0x7FFu);                  // 0..2046
                float wgt = (v & 0x800u) ? apod[j] : 0.0f;
                float a   = (float)(v >> 12) * (1.0f / 1048576.0f);

                float4 s0 = s_sino[j * NT + k0];
                float4 s1 = s_sino[j * NT + k0 + 1];

                float wa = wgt * a;
                float w0 = wgt - wa;

                unsigned long long w0p = pk2(w0, w0), wap = pk2(wa, wa);
                acc_xy = fma2(w0p, pk2(s0.x, s0.y), fma2(wap, pk2(s1.x, s1.y), acc_xy));
                acc_zw = fma2(w0p, pk2(s0.z, s0.w), fma2(wap, pk2(s1.z, s1.w), acc_zw));
            }

            float ax, ay, az, aw;
            upk2(acc_xy, ax, ay);
            upk2(acc_zw, az, aw);

            const int p = px0 + g * THREADS + tid;
            atomicAdd(out + 0 * NPIX + p, ax);
            atomicAdd(out + 1 * NPIX + p, ay);
            atomicAdd(out + 2 * NPIX + p, az);
            atomicAdd(out + 3 * NPIX + p, aw);

            L = N;
        }

        w = seg_end;
    }
}

// ---------------------------------------------------------------------------
extern "C" void kernel_launch(void* const* d_in, const int* in_sizes, int n_in,
                              void* d_out, int out_size) {
    const float*  sino = (const float*)d_in[0];
    const float4* lut4 = (const float4*)d_in[1];
    float*        out  = (float*)d_out;

    cudaFuncSetAttribute(bp_main_kernel,
                         cudaFuncAttributeMaxDynamicSharedMemorySize,
                         DC * NT * (int)sizeof(float4));

    lut_pack_kernel<<<1024, 512>>>(lut4, (float4*)out);

    bp_main_kernel<<<NBLK, THREADS, DC * NT * sizeof(float4)>>>(sino, out);
}